// round 15
// baseline (speedup 1.0000x reference)
#include <cuda_runtime.h>

// ---------------------------------------------------------------------------
// MultiUniverseToposAttention  B=1 S=512 H=8 DH=64 DM=512 TOP_K=2
//   1) k_gemm_qkv (z=0..2): Q,K,V = x @ sig(W)^T via 3xTF32 mma.sync
//      (z=3): router gates (logits -> softmax -> top2), reads x only
//   2) k_rope_sig (grid 520+256): RoPE+sigmoid -> head-major Qs,Ks,Vh + Ksum;
//      per-head ballot-scan compaction; tail blocks zero `out`
//   3) k_attn (128 thr, 16-q tiles, split-K x4): truth = 1-(summax-Ksum)/64
//      partials written SLOT-major: pacc[z][h][slot][d], prs[z][h][slot]
//   4) k_gemm_out_sp: per-head gather-GEMM; A-tile = sum of 4 splits (in-reg,
//      coalesced); row scale f=gate/(rs+eps) applied in epilogue; scatter-
//      atomicAdd (2 commutative fp32 adds per element -> deterministic)
// ---------------------------------------------------------------------------

#define S_    512
#define DM_   512
#define H_    8
#define DH_   64
#define HALF_ 32
#define NSPL  4
#define KPS   (S_ / NSPL)
#define QT    16

__device__ float g_Q [S_ * DM_];
__device__ float g_K [S_ * DM_];
__device__ float g_V [S_ * DM_];
__device__ float g_Qs[H_][S_][DH_];
__device__ float g_Ks[H_][S_][DH_];
__device__ float g_Vh[H_][S_][DH_];
__device__ float g_Ksum[H_][S_];
__device__ float g_gate[S_][H_];
__device__ int   g_qidx[H_][S_];
__device__ int   g_qcnt[H_];
__device__ float g_pacc[NSPL][H_][S_][DH_];   // slot-major split partials
__device__ float g_prs [NSPL][H_][S_];

__device__ __forceinline__ float sigf(float x) {
    return 1.0f / (1.0f + __expf(-x));
}
__device__ __forceinline__ unsigned f2tf(float x) {
    unsigned u;
    asm("cvt.rna.tf32.f32 %0, %1;" : "=r"(u) : "f"(x));
    return u;
}
__device__ __forceinline__ void hilo(float v, float& h, float& l) {
    unsigned hu = f2tf(v);
    h = __uint_as_float(hu);
    l = __uint_as_float(f2tf(v - h));
}
__device__ __forceinline__ void mma_tf32(float c[4], const unsigned a[4],
                                         const unsigned b[2]) {
    asm volatile(
        "mma.sync.aligned.m16n8k8.row.col.f32.tf32.tf32.f32 "
        "{%0,%1,%2,%3}, {%4,%5,%6,%7}, {%8,%9}, {%0,%1,%2,%3};"
        : "+f"(c[0]), "+f"(c[1]), "+f"(c[2]), "+f"(c[3])
        : "r"(a[0]), "r"(a[1]), "r"(a[2]), "r"(a[3]), "r"(b[0]), "r"(b[1]));
}

// ---------------------------------------------------------------------------
// Dense 3xTF32 GEMM (R11-validated): C = A @ sig(W)^T; 64x64 tile, BK=32.
// ---------------------------------------------------------------------------
__device__ __forceinline__ void gemm_tf32_body(const float* __restrict__ A,
                                               const float* __restrict__ W,
                                               float* __restrict__ C) {
    __shared__ float Ah[64][36];
    __shared__ float Al[64][36];
    __shared__ float Bh[64][36];
    __shared__ float Bl[64][36];

    const int t    = threadIdx.x;
    const int lane = t & 31, w = t >> 5;
    const int wm = w & 1, wn = w >> 1;
    const int g  = lane >> 2, tg = lane & 3;
    const int m0 = blockIdx.y * 64, n0 = blockIdx.x * 64;

    const int rowL = t >> 2;
    const int cL   = (t & 3) << 3;

    float4 pa0, pa1, pb0, pb1;
    {
        const float* Ar = A + (m0 + rowL) * DM_;
        const float* Wr = W + (n0 + rowL) * DM_;
        pa0 = *(const float4*)&Ar[cL];
        pa1 = *(const float4*)&Ar[cL + 4];
        pb0 = *(const float4*)&Wr[cL];
        pb1 = *(const float4*)&Wr[cL + 4];
    }

    float acc[2][2][4] = {};

    for (int ch = 0; ch < 16; ch++) {
        __syncthreads();
        {
            float4 h4, l4;
            hilo(pa0.x, h4.x, l4.x); hilo(pa0.y, h4.y, l4.y);
            hilo(pa0.z, h4.z, l4.z); hilo(pa0.w, h4.w, l4.w);
            *(float4*)&Ah[rowL][cL] = h4;
            *(float4*)&Al[rowL][cL] = l4;
            hilo(pa1.x, h4.x, l4.x); hilo(pa1.y, h4.y, l4.y);
            hilo(pa1.z, h4.z, l4.z); hilo(pa1.w, h4.w, l4.w);
            *(float4*)&Ah[rowL][cL + 4] = h4;
            *(float4*)&Al[rowL][cL + 4] = l4;
            hilo(sigf(pb0.x), h4.x, l4.x); hilo(sigf(pb0.y), h4.y, l4.y);
            hilo(sigf(pb0.z), h4.z, l4.z); hilo(sigf(pb0.w), h4.w, l4.w);
            *(float4*)&Bh[rowL][cL] = h4;
            *(float4*)&Bl[rowL][cL] = l4;
            hilo(sigf(pb1.x), h4.x, l4.x); hilo(sigf(pb1.y), h4.y, l4.y);
            hilo(sigf(pb1.z), h4.z, l4.z); hilo(sigf(pb1.w), h4.w, l4.w);
            *(float4*)&Bh[rowL][cL + 4] = h4;
            *(float4*)&Bl[rowL][cL + 4] = l4;
        }
        __syncthreads();

        if (ch < 15) {
            const int k0 = (ch + 1) * 32;
            const float* Ar = A + (m0 + rowL) * DM_ + k0;
            const float* Wr = W + (n0 + rowL) * DM_ + k0;
            pa0 = *(const float4*)&Ar[cL];
            pa1 = *(const float4*)&Ar[cL + 4];
            pb0 = *(const float4*)&Wr[cL];
            pb1 = *(const float4*)&Wr[cL + 4];
        }

#pragma unroll
        for (int ks = 0; ks < 4; ks++) {
            const int kb = ks * 8;
            unsigned ah[2][4], al[2][4];
#pragma unroll
            for (int i = 0; i < 2; i++) {
                const int rm = wm * 32 + i * 16 + g;
                ah[i][0] = __float_as_uint(Ah[rm    ][kb + tg]);
                ah[i][1] = __float_as_uint(Ah[rm + 8][kb + tg]);
                ah[i][2] = __float_as_uint(Ah[rm    ][kb + tg + 4]);
                ah[i][3] = __float_as_uint(Ah[rm + 8][kb + tg + 4]);
                al[i][0] = __float_as_uint(Al[rm    ][kb + tg]);
                al[i][1] = __float_as_uint(Al[rm + 8][kb + tg]);
                al[i][2] = __float_as_uint(Al[rm    ][kb + tg + 4]);
                al[i][3] = __float_as_uint(Al[rm + 8][kb + tg + 4]);
            }
            unsigned bh[2][2], bl[2][2];
#pragma unroll
            for (int j = 0; j < 2; j++) {
                const int rn = wn * 16 + j * 8 + g;
                bh[j][0] = __float_as_uint(Bh[rn][kb + tg]);
                bh[j][1] = __float_as_uint(Bh[rn][kb + tg + 4]);
                bl[j][0] = __float_as_uint(Bl[rn][kb + tg]);
                bl[j][1] = __float_as_uint(Bl[rn][kb + tg + 4]);
            }
#pragma unroll
            for (int i = 0; i < 2; i++)
#pragma unroll
                for (int j = 0; j < 2; j++) {
                    mma_tf32(acc[i][j], ah[i], bl[j]);
                    mma_tf32(acc[i][j], al[i], bh[j]);
                    mma_tf32(acc[i][j], ah[i], bh[j]);
                }
        }
    }

#pragma unroll
    for (int i = 0; i < 2; i++)
#pragma unroll
        for (int j = 0; j < 2; j++) {
            const int gm = m0 + wm * 32 + i * 16 + g;
            const int gn = n0 + wn * 16 + j * 8 + tg * 2;
            *(float2*)&C[gm * DM_ + gn]       = make_float2(acc[i][j][0], acc[i][j][1]);
            *(float2*)&C[(gm + 8) * DM_ + gn] = make_float2(acc[i][j][2], acc[i][j][3]);
        }
}

// ---------------------------------------------------------------------------
// Router body (z=3): 64 blocks x 8 warps = 512 tokens; warp per token.
// ---------------------------------------------------------------------------
__device__ __forceinline__ void router_body(const float* __restrict__ x,
                                            const float* __restrict__ Wr) {
    const int t = threadIdx.x;
    const int lane = t & 31, w = t >> 5;
    const int s = (blockIdx.y * 8 + blockIdx.x) * 8 + w;

    const float* xs = x + s * DM_;
    float acc[H_] = {};
#pragma unroll 4
    for (int ds = 0; ds < 16; ds++) {
        const int d = lane + 32 * ds;
        const float xv = xs[d];
#pragma unroll
        for (int h = 0; h < H_; h++)
            acc[h] = fmaf(xv, sigf(Wr[h * DM_ + d]), acc[h]);
    }
#pragma unroll
    for (int h = 0; h < H_; h++)
#pragma unroll
        for (int o = 16; o > 0; o >>= 1)
            acc[h] += __shfl_xor_sync(0xFFFFFFFFu, acc[h], o);

    if (lane == 0) {
        float m = acc[0];
#pragma unroll
        for (int i = 1; i < H_; i++) m = fmaxf(m, acc[i]);
        float e[H_];
        float Z = 0.f;
#pragma unroll
        for (int i = 0; i < H_; i++) { e[i] = expf(acc[i] - m); Z += e[i]; }
        int i0 = 0;
#pragma unroll
        for (int i = 1; i < H_; i++) if (e[i] > e[i0]) i0 = i;
        int i1 = (i0 == 0) ? 1 : 0;
#pragma unroll
        for (int i = 0; i < H_; i++) if (i != i0 && e[i] > e[i1]) i1 = i;
        float p0 = e[i0] / Z, p1 = e[i1] / Z;
        float inv = 1.0f / (p0 + p1 + 1e-9f);
#pragma unroll
        for (int i = 0; i < H_; i++) g_gate[s][i] = 0.f;
        g_gate[s][i0] = p0 * inv;
        g_gate[s][i1] = p1 * inv;
    }
}

__global__ void __launch_bounds__(256)
k_gemm_qkv(const float* __restrict__ x,
           const float* __restrict__ Wq,
           const float* __restrict__ Wk,
           const float* __restrict__ Wv,
           const float* __restrict__ Wr) {
    if (blockIdx.z == 3) { router_body(x, Wr); return; }
    const float* W;
    float* C;
    if (blockIdx.z == 0)      { W = Wq; C = g_Q; }
    else if (blockIdx.z == 1) { W = Wk; C = g_K; }
    else                      { W = Wv; C = g_V; }
    gemm_tf32_body(x, W, C);
}

// ---------------------------------------------------------------------------
// RoPE + sigmoid + head-major transpose + Ksum (blocks 0..511)
// Per-head compaction (blocks 512..519); zero `out` (blocks 520..775)
// ---------------------------------------------------------------------------
__global__ void __launch_bounds__(256)
k_rope_sig(const float* __restrict__ fc, const float* __restrict__ fs,
           float* __restrict__ out) {
    const int t = threadIdx.x;

    if (blockIdx.x >= S_ + H_) {
        const int zb = blockIdx.x - (S_ + H_);
        *(float4*)&out[(zb * 256 + t) * 4] = make_float4(0.f, 0.f, 0.f, 0.f);
        return;
    }

    if (blockIdx.x >= S_) {
        const int h = blockIdx.x - S_;
        const int lane = t & 31, w = t >> 5;
        __shared__ int swc[16];
        const int s0 = t, s1 = t + 256;
        const int f0 = (g_gate[s0][h] != 0.f) ? 1 : 0;
        const int f1 = (g_gate[s1][h] != 0.f) ? 1 : 0;
        const unsigned b0 = __ballot_sync(0xFFFFFFFFu, f0);
        const unsigned b1 = __ballot_sync(0xFFFFFFFFu, f1);
        if (lane == 0) { swc[w] = __popc(b0); swc[8 + w] = __popc(b1); }
        __syncthreads();
        int pre0 = 0, tot0 = 0;
#pragma unroll
        for (int i = 0; i < 8; i++) {
            if (i < w) pre0 += swc[i];
            tot0 += swc[i];
        }
        int pre1 = tot0;
#pragma unroll
        for (int i = 0; i < 8; i++) if (i < w) pre1 += swc[8 + i];
        const unsigned lm = (1u << lane) - 1u;
        if (f0) g_qidx[h][pre0 + __popc(b0 & lm)] = s0;
        if (f1) g_qidx[h][pre1 + __popc(b1 & lm)] = s1;
        if (t == 0) {
            int tot = tot0;
#pragma unroll
            for (int i = 0; i < 8; i++) tot += swc[8 + i];
            g_qcnt[h] = tot;
        }
        return;
    }

    const int s = blockIdx.x;
    const int h = t >> 5, p = t & 31;

    const float c  = fc[s * HALF_ + p];
    const float sn = fs[s * HALF_ + p];
    const int base = s * DM_ + h * DH_ + 2 * p;

    float q0 = g_Q[base], q1 = g_Q[base + 1];
    float k0 = g_K[base], k1 = g_K[base + 1];
    float qr0 = q0 * c - q1 * sn, qr1 = q0 * sn + q1 * c;
    float kr0 = k0 * c - k1 * sn, kr1 = k0 * sn + k1 * c;
    float ks0 = sigf(kr0), ks1 = sigf(kr1);
    g_Qs[h][s][2 * p]     = sigf(qr0);
    g_Qs[h][s][2 * p + 1] = sigf(qr1);
    g_Ks[h][s][2 * p]     = ks0;
    g_Ks[h][s][2 * p + 1] = ks1;

    float v = ks0 + ks1;
#pragma unroll
    for (int o = 16; o > 0; o >>= 1)
        v += __shfl_xor_sync(0xFFFFFFFFu, v, o);
    if (p == 0) g_Ksum[h][s] = v;

#pragma unroll
    for (int j = t; j < DM_; j += 256) {
        int h2 = j >> 6, d = j & 63;
        g_Vh[h2][s][d] = g_V[s * DM_ + j];
    }
}

// ---------------------------------------------------------------------------
// Attention: 128 threads, 16 compacted queries, split-K x NSPL (=4).
// Writes slot-major partials: pacc[z][h][slot][d], prs[z][h][slot].
// ---------------------------------------------------------------------------
__global__ void __launch_bounds__(128)
k_attn() {
    const int h   = blockIdx.y;
    const int cnt = g_qcnt[h];
    const int q0  = blockIdx.x * QT;
    if (q0 >= cnt) return;
    const int nq  = min(QT, cnt - q0);
    const int z   = blockIdx.z;
    const int t   = threadIdx.x;

    __shared__ float Qs_s[QT][68];
    __shared__ float Ks_s[32][68];
    __shared__ float Vs_s[32][68];
    __shared__ float Tr  [QT][33];
    __shared__ float rs_s[QT];
    __shared__ float ksum_s[32];
    __shared__ int   sidx[QT];

    if (t < QT) {
        sidx[t] = g_qidx[h][q0 + ((t < nq) ? t : 0)];
        rs_s[t] = 0.f;
    }
    __syncthreads();

#pragma unroll
    for (int j = t; j < QT * 16; j += 128) {
        int r = j >> 4, c4 = (j & 15) << 2;
        *(float4*)&Qs_s[r][c4] = *(const float4*)&g_Qs[h][sidx[r]][c4];
    }

    const int qq = t >> 4, kk = t & 15;
    const int qa = 2 * qq, qb = qa + 1;
    const int ka = 2 * kk, kb = ka + 1;

    const int qf = t >> 3;
    const int dg = (t & 7) << 3;
    float acc[8] = {};
    const bool qf_active = (qf < nq);

    for (int kt = 0; kt < KPS / 32; kt++) {
        const int k0 = z * KPS + kt * 32;
        __syncthreads();
#pragma unroll
        for (int j = t; j < 32 * 16; j += 128) {
            int r = j >> 4, c4 = (j & 15) << 2;
            *(float4*)&Ks_s[r][c4] = *(const float4*)&g_Ks[h][k0 + r][c4];
            *(float4*)&Vs_s[r][c4] = *(const float4*)&g_Vh[h][k0 + r][c4];
        }
        if (t < 32) ksum_s[t] = g_Ksum[h][k0 + t];
        __syncthreads();

        {
            float s00 = 0.f, s01 = 0.f, s10 = 0.f, s11 = 0.f;
#pragma unroll
            for (int d = 0; d < 64; d += 4) {
                float4 A0 = *(const float4*)&Qs_s[qa][d];
                float4 A1 = *(const float4*)&Qs_s[qb][d];
                float4 B0 = *(const float4*)&Ks_s[ka][d];
                float4 B1 = *(const float4*)&Ks_s[kb][d];
                s00 += fmaxf(A0.x, B0.x) + fmaxf(A0.y, B0.y)
                     + fmaxf(A0.z, B0.z) + fmaxf(A0.w, B0.w);
                s01 += fmaxf(A0.x, B1.x) + fmaxf(A0.y, B1.y)
                     + fmaxf(A0.z, B1.z) + fmaxf(A0.w, B1.w);
                s10 += fmaxf(A1.x, B0.x) + fmaxf(A1.y, B0.y)
                     + fmaxf(A1.z, B0.z) + fmaxf(A1.w, B0.w);
                s11 += fmaxf(A1.x, B1.x) + fmaxf(A1.y, B1.y)
                     + fmaxf(A1.z, B1.z) + fmaxf(A1.w, B1.w);
            }
            const float c = 1.0f / 64.0f;
            const float ksa = ksum_s[ka], ksb = ksum_s[kb];
            Tr[qa][ka] = 1.0f - (s00 - ksa) * c;
            Tr[qa][kb] = 1.0f - (s01 - ksb) * c;
            Tr[qb][ka] = 1.0f - (s10 - ksa) * c;
            Tr[qb][kb] = 1.0f - (s11 - ksb) * c;
        }
        __syncthreads();

        if (t < QT) {
            float r = 0.f;
#pragma unroll
            for (int k = 0; k < 32; k++) r += Tr[t][k];
            rs_s[t] += r;
        }

#pragma unroll
        for (int k = 0; k < 32; k++) {
            float tv = Tr[qf][k];
            float4 v0 = *(const float4*)&Vs_s[k][dg];
            float4 v1 = *(const float4*)&Vs_s[k][dg + 4];
            acc[0] = fmaf(tv, v0.x, acc[0]);
            acc[1] = fmaf(tv, v0.y, acc[1]);
            acc[2] = fmaf(tv, v0.z, acc[2]);
            acc[3] = fmaf(tv, v0.w, acc[3]);
            acc[4] = fmaf(tv, v1.x, acc[4]);
            acc[5] = fmaf(tv, v1.y, acc[5]);
            acc[6] = fmaf(tv, v1.z, acc[6]);
            acc[7] = fmaf(tv, v1.w, acc[7]);
        }
    }
    __syncthreads();

    if (qf_active) {
        *(float4*)&g_pacc[z][h][q0 + qf][dg] =
            make_float4(acc[0], acc[1], acc[2], acc[3]);
        *(float4*)&g_pacc[z][h][q0 + qf][dg + 4] =
            make_float4(acc[4], acc[5], acc[6], acc[7]);
    }
    if (t < nq) g_prs[z][h][q0 + t] = rs_s[t];
}

// ---------------------------------------------------------------------------
// Sparse output GEMM with fused normalization:
//   A[sl][k] = sum_z pacc[z][h][sl][k]   (coalesced, L2-resident)
//   out[qidx[sl]][n] += f_sl * (A @ sig(Wo_h)^T),  f = gate/(rs+eps)
// K=64 (2 BK=32 chunks), scatter-atomicAdd epilogue.
// ---------------------------------------------------------------------------
__global__ void __launch_bounds__(256)
k_gemm_out_sp(const float* __restrict__ Wo, float* __restrict__ out) {
    const int h   = blockIdx.z;
    const int cnt = g_qcnt[h];
    const int m0  = blockIdx.y * 64;
    if (m0 >= cnt) return;
    const int n0  = blockIdx.x * 64;

    __shared__ float As[64][36];
    __shared__ float Bs[64][36];
    __shared__ float fs_s[64];
    __shared__ int   sidx_s[64];

    const int t    = threadIdx.x;
    const int lane = t & 31, w = t >> 5;
    const int wm = w & 1, wn = w >> 1;
    const int g  = lane >> 2, tg = lane & 3;
    const int rowL = t >> 2;
    const int cL   = (t & 3) << 3;

    // prologue: per-slot scale + token id (f=0 for pad slots)
    if (t < 64) {
        const int sl = m0 + t;
        float f = 0.f;
        int s = 0;
        if (sl < cnt) {
            s = g_qidx[h][sl];
            float rs = 0.f;
#pragma unroll
            for (int z = 0; z < NSPL; z++) rs += g_prs[z][h][sl];
            f = g_gate[s][h] / (rs + 1e-9f);
        }
        fs_s[t] = f;
        sidx_s[t] = s;
    }

    float acc[2][2][4] = {};

    for (int ch = 0; ch < 2; ch++) {
        const int k0 = ch * 32;
        const int sl = m0 + rowL;                 // <= 511 always
        float4 a0 = make_float4(0.f, 0.f, 0.f, 0.f);
        float4 a1 = make_float4(0.f, 0.f, 0.f, 0.f);
#pragma unroll
        for (int z = 0; z < NSPL; z++) {
            float4 p0 = *(const float4*)&g_pacc[z][h][sl][k0 + cL];
            float4 p1 = *(const float4*)&g_pacc[z][h][sl][k0 + cL + 4];
            a0.x += p0.x; a0.y += p0.y; a0.z += p0.z; a0.w += p0.w;
            a1.x += p1.x; a1.y += p1.y; a1.z += p1.z; a1.w += p1.w;
        }
        const float* Wr = Wo + (n0 + rowL) * DM_ + h * DH_ + k0 + cL;
        float4 b0 = *(const float4*)Wr;
        float4 b1 = *(const float4*)(Wr + 4);
        __syncthreads();
        *(float4*)&As[rowL][cL]     = a0;
        *(float4*)&As[rowL][cL + 4] = a1;
        *(float4*)&Bs[rowL][cL] =
            make_float4(sigf(b0.x), sigf(b0.y), sigf(b0.z), sigf(b0.w));
        *(float4*)&Bs[rowL][cL + 4] =
            make_float4(sigf(b1.x), sigf(b1.y), sigf(b1.z), sigf(b1.w));
        __syncthreads();

#pragma unroll
        for (int ks = 0; ks < 4; ks++) {
            const int kb = ks * 8;
            unsigned ah[2][4], al[2][4];
#pragma unroll
            for (int i = 0; i < 2; i++) {
                const int rm = wm * 32 + i * 16 + g;
                float v0 = As[rm    ][kb + tg];
                float v1 = As[rm + 8][kb + tg];
                float v2 = As[rm    ][kb + tg + 4];
                float v3 = As[rm + 8][kb + tg + 4];
                float hh, ll;
                hilo(v0, hh, ll); ah[i][0] = __float_as_uint(hh); al[i][0] = __float_as_uint(ll);
                hilo(v1, hh, ll); ah[i][1] = __float_as_uint(hh); al[i][1] = __float_as_uint(ll);
                hilo(v2, hh, ll); ah[i][2] = __float_as_uint(hh); al[i][2] = __float_as_uint(ll);
                hilo(v3, hh, ll); ah[i][3] = __float_as_uint(hh); al[i][3] = __float_as_uint(ll);
            }
            unsigned bh[2][2], bl[2][2];
#pragma unroll
            for (int j = 0; j < 2; j++) {
                const int rn = wn * 16 + j * 8 + g;
                float v0 = Bs[rn][kb + tg];
                float v1 = Bs[rn][kb + tg + 4];
                float hh, ll;
                hilo(v0, hh, ll); bh[j][0] = __float_as_uint(hh); bl[j][0] = __float_as_uint(ll);
                hilo(v1, hh, ll); bh[j][1] = __float_as_uint(hh); bl[j][1] = __float_as_uint(ll);
            }
#pragma unroll
            for (int i = 0; i < 2; i++)
#pragma unroll
                for (int j = 0; j < 2; j++) {
                    mma_tf32(acc[i][j], ah[i], bl[j]);
                    mma_tf32(acc[i][j], al[i], bh[j]);
                    mma_tf32(acc[i][j], ah[i], bh[j]);
                }
        }
    }

    // scatter epilogue with fused row scale
#pragma unroll
    for (int i = 0; i < 2; i++)
#pragma unroll
        for (int j = 0; j < 2; j++) {
            const int l0 = wm * 32 + i * 16 + g;    // local slot in [0,64)
            const int l1 = l0 + 8;
            const int gn = n0 + wn * 16 + j * 8 + tg * 2;
            if (m0 + l0 < cnt) {
                const int s = sidx_s[l0];
                const float f = fs_s[l0];
                atomicAdd(&out[s * DM_ + gn],     acc[i][j][0] * f);
                atomicAdd(&out[s * DM_ + gn + 1], acc[i][j][1] * f);
            }
            if (m0 + l1 < cnt) {
                const int s = sidx_s[l1];
                const float f = fs_s[l1];
                atomicAdd(&out[s * DM_ + gn],     acc[i][j][2] * f);
                atomicAdd(&out[s * DM_ + gn + 1], acc[i][j][3] * f);
            }
        }
}

// ---------------------------------------------------------------------------
extern "C" void kernel_launch(void* const* d_in, const int* in_sizes, int n_in,
                              void* d_out, int out_size) {
    const float* x  = (const float*)d_in[0];
    const float* fc = (const float*)d_in[1];
    const float* fs = (const float*)d_in[2];
    const float* Wq = (const float*)d_in[3];
    const float* Wk = (const float*)d_in[4];
    const float* Wv = (const float*)d_in[5];
    const float* Wo = (const float*)d_in[6];
    const float* Wr = (const float*)d_in[7];
    float* out = (float*)d_out;

    k_gemm_qkv   <<<dim3(8, 8, 4), 256>>>(x, Wq, Wk, Wv, Wr);
    k_rope_sig   <<<S_ + H_ + 256, 256>>>(fc, fs, out);
    k_attn       <<<dim3(S_ / QT, H_, NSPL), 128>>>();
    k_gemm_out_sp<<<dim3(8, 8, H_), 256>>>(Wo, out);
}

// round 16
// speedup vs baseline: 1.1055x; 1.1055x over previous
#include <cuda_runtime.h>

// ---------------------------------------------------------------------------
// MultiUniverseToposAttention  B=1 S=512 H=8 DH=64 DM=512 TOP_K=2
//   1) k_gemm_qkv (z=0..2): Q,K,V = x @ sig(W)^T via 3xTF32 mma.sync
//      (z=3): router gates (logits -> softmax -> top2), reads x only
//   2) k_rope_sig (grid 520+256): RoPE+sigmoid -> head-major Qs,Ks,Vh + Ksum;
//      per-head ballot-scan compaction; tail blocks zero `out`
//   3) k_attn (128 thr, 16-q tiles, split-K x8): truth = 1-(summax-Ksum)/64
//      partials SLOT-major: pacc[z][h][slot][d], prs[z][h][slot]
//   4) k_norm: coalesced slot-major combine + gate -> Gc[h][slot][64]
//   5) k_gemm_out_sp: per-head gather-GEMM (K=64) on Gc, scatter-atomicAdd
//      epilogue (2 commutative fp32 adds per element -> deterministic)
// ---------------------------------------------------------------------------

#define S_    512
#define DM_   512
#define H_    8
#define DH_   64
#define HALF_ 32
#define NSPL  8
#define KPS   (S_ / NSPL)
#define QT    16

__device__ float g_Q [S_ * DM_];
__device__ float g_K [S_ * DM_];
__device__ float g_V [S_ * DM_];
__device__ float g_Qs[H_][S_][DH_];
__device__ float g_Ks[H_][S_][DH_];
__device__ float g_Vh[H_][S_][DH_];
__device__ float g_Ksum[H_][S_];
__device__ float g_gate[S_][H_];
__device__ int   g_qidx[H_][S_];
__device__ int   g_qcnt[H_];
__device__ float g_Gc[H_][S_][DH_];           // compacted, gated attn output
__device__ float g_pacc[NSPL][H_][S_][DH_];   // slot-major split partials
__device__ float g_prs [NSPL][H_][S_];

__device__ __forceinline__ float sigf(float x) {
    return 1.0f / (1.0f + __expf(-x));
}
__device__ __forceinline__ unsigned f2tf(float x) {
    unsigned u;
    asm("cvt.rna.tf32.f32 %0, %1;" : "=r"(u) : "f"(x));
    return u;
}
__device__ __forceinline__ void hilo(float v, float& h, float& l) {
    unsigned hu = f2tf(v);
    h = __uint_as_float(hu);
    l = __uint_as_float(f2tf(v - h));
}
__device__ __forceinline__ void mma_tf32(float c[4], const unsigned a[4],
                                         const unsigned b[2]) {
    asm volatile(
        "mma.sync.aligned.m16n8k8.row.col.f32.tf32.tf32.f32 "
        "{%0,%1,%2,%3}, {%4,%5,%6,%7}, {%8,%9}, {%0,%1,%2,%3};"
        : "+f"(c[0]), "+f"(c[1]), "+f"(c[2]), "+f"(c[3])
        : "r"(a[0]), "r"(a[1]), "r"(a[2]), "r"(a[3]), "r"(b[0]), "r"(b[1]));
}

// ---------------------------------------------------------------------------
// Dense 3xTF32 GEMM (R11-validated): C = A @ sig(W)^T; 64x64 tile, BK=32.
// ---------------------------------------------------------------------------
__device__ __forceinline__ void gemm_tf32_body(const float* __restrict__ A,
                                               const float* __restrict__ W,
                                               float* __restrict__ C) {
    __shared__ float Ah[64][36];
    __shared__ float Al[64][36];
    __shared__ float Bh[64][36];
    __shared__ float Bl[64][36];

    const int t    = threadIdx.x;
    const int lane = t & 31, w = t >> 5;
    const int wm = w & 1, wn = w >> 1;
    const int g  = lane >> 2, tg = lane & 3;
    const int m0 = blockIdx.y * 64, n0 = blockIdx.x * 64;

    const int rowL = t >> 2;
    const int cL   = (t & 3) << 3;

    float4 pa0, pa1, pb0, pb1;
    {
        const float* Ar = A + (m0 + rowL) * DM_;
        const float* Wr = W + (n0 + rowL) * DM_;
        pa0 = *(const float4*)&Ar[cL];
        pa1 = *(const float4*)&Ar[cL + 4];
        pb0 = *(const float4*)&Wr[cL];
        pb1 = *(const float4*)&Wr[cL + 4];
    }

    float acc[2][2][4] = {};

    for (int ch = 0; ch < 16; ch++) {
        __syncthreads();
        {
            float4 h4, l4;
            hilo(pa0.x, h4.x, l4.x); hilo(pa0.y, h4.y, l4.y);
            hilo(pa0.z, h4.z, l4.z); hilo(pa0.w, h4.w, l4.w);
            *(float4*)&Ah[rowL][cL] = h4;
            *(float4*)&Al[rowL][cL] = l4;
            hilo(pa1.x, h4.x, l4.x); hilo(pa1.y, h4.y, l4.y);
            hilo(pa1.z, h4.z, l4.z); hilo(pa1.w, h4.w, l4.w);
            *(float4*)&Ah[rowL][cL + 4] = h4;
            *(float4*)&Al[rowL][cL + 4] = l4;
            hilo(sigf(pb0.x), h4.x, l4.x); hilo(sigf(pb0.y), h4.y, l4.y);
            hilo(sigf(pb0.z), h4.z, l4.z); hilo(sigf(pb0.w), h4.w, l4.w);
            *(float4*)&Bh[rowL][cL] = h4;
            *(float4*)&Bl[rowL][cL] = l4;
            hilo(sigf(pb1.x), h4.x, l4.x); hilo(sigf(pb1.y), h4.y, l4.y);
            hilo(sigf(pb1.z), h4.z, l4.z); hilo(sigf(pb1.w), h4.w, l4.w);
            *(float4*)&Bh[rowL][cL + 4] = h4;
            *(float4*)&Bl[rowL][cL + 4] = l4;
        }
        __syncthreads();

        if (ch < 15) {
            const int k0 = (ch + 1) * 32;
            const float* Ar = A + (m0 + rowL) * DM_ + k0;
            const float* Wr = W + (n0 + rowL) * DM_ + k0;
            pa0 = *(const float4*)&Ar[cL];
            pa1 = *(const float4*)&Ar[cL + 4];
            pb0 = *(const float4*)&Wr[cL];
            pb1 = *(const float4*)&Wr[cL + 4];
        }

#pragma unroll
        for (int ks = 0; ks < 4; ks++) {
            const int kb = ks * 8;
            unsigned ah[2][4], al[2][4];
#pragma unroll
            for (int i = 0; i < 2; i++) {
                const int rm = wm * 32 + i * 16 + g;
                ah[i][0] = __float_as_uint(Ah[rm    ][kb + tg]);
                ah[i][1] = __float_as_uint(Ah[rm + 8][kb + tg]);
                ah[i][2] = __float_as_uint(Ah[rm    ][kb + tg + 4]);
                ah[i][3] = __float_as_uint(Ah[rm + 8][kb + tg + 4]);
                al[i][0] = __float_as_uint(Al[rm    ][kb + tg]);
                al[i][1] = __float_as_uint(Al[rm + 8][kb + tg]);
                al[i][2] = __float_as_uint(Al[rm    ][kb + tg + 4]);
                al[i][3] = __float_as_uint(Al[rm + 8][kb + tg + 4]);
            }
            unsigned bh[2][2], bl[2][2];
#pragma unroll
            for (int j = 0; j < 2; j++) {
                const int rn = wn * 16 + j * 8 + g;
                bh[j][0] = __float_as_uint(Bh[rn][kb + tg]);
                bh[j][1] = __float_as_uint(Bh[rn][kb + tg + 4]);
                bl[j][0] = __float_as_uint(Bl[rn][kb + tg]);
                bl[j][1] = __float_as_uint(Bl[rn][kb + tg + 4]);
            }
#pragma unroll
            for (int i = 0; i < 2; i++)
#pragma unroll
                for (int j = 0; j < 2; j++) {
                    mma_tf32(acc[i][j], ah[i], bl[j]);
                    mma_tf32(acc[i][j], al[i], bh[j]);
                    mma_tf32(acc[i][j], ah[i], bh[j]);
                }
        }
    }

#pragma unroll
    for (int i = 0; i < 2; i++)
#pragma unroll
        for (int j = 0; j < 2; j++) {
            const int gm = m0 + wm * 32 + i * 16 + g;
            const int gn = n0 + wn * 16 + j * 8 + tg * 2;
            *(float2*)&C[gm * DM_ + gn]       = make_float2(acc[i][j][0], acc[i][j][1]);
            *(float2*)&C[(gm + 8) * DM_ + gn] = make_float2(acc[i][j][2], acc[i][j][3]);
        }
}

// ---------------------------------------------------------------------------
// Router body (z=3): 64 blocks x 8 warps = 512 tokens; warp per token.
// ---------------------------------------------------------------------------
__device__ __forceinline__ void router_body(const float* __restrict__ x,
                                            const float* __restrict__ Wr) {
    const int t = threadIdx.x;
    const int lane = t & 31, w = t >> 5;
    const int s = (blockIdx.y * 8 + blockIdx.x) * 8 + w;

    const float* xs = x + s * DM_;
    float acc[H_] = {};
#pragma unroll 4
    for (int ds = 0; ds < 16; ds++) {
        const int d = lane + 32 * ds;
        const float xv = xs[d];
#pragma unroll
        for (int h = 0; h < H_; h++)
            acc[h] = fmaf(xv, sigf(Wr[h * DM_ + d]), acc[h]);
    }
#pragma unroll
    for (int h = 0; h < H_; h++)
#pragma unroll
        for (int o = 16; o > 0; o >>= 1)
            acc[h] += __shfl_xor_sync(0xFFFFFFFFu, acc[h], o);

    if (lane == 0) {
        float m = acc[0];
#pragma unroll
        for (int i = 1; i < H_; i++) m = fmaxf(m, acc[i]);
        float e[H_];
        float Z = 0.f;
#pragma unroll
        for (int i = 0; i < H_; i++) { e[i] = expf(acc[i] - m); Z += e[i]; }
        int i0 = 0;
#pragma unroll
        for (int i = 1; i < H_; i++) if (e[i] > e[i0]) i0 = i;
        int i1 = (i0 == 0) ? 1 : 0;
#pragma unroll
        for (int i = 0; i < H_; i++) if (i != i0 && e[i] > e[i1]) i1 = i;
        float p0 = e[i0] / Z, p1 = e[i1] / Z;
        float inv = 1.0f / (p0 + p1 + 1e-9f);
#pragma unroll
        for (int i = 0; i < H_; i++) g_gate[s][i] = 0.f;
        g_gate[s][i0] = p0 * inv;
        g_gate[s][i1] = p1 * inv;
    }
}

__global__ void __launch_bounds__(256)
k_gemm_qkv(const float* __restrict__ x,
           const float* __restrict__ Wq,
           const float* __restrict__ Wk,
           const float* __restrict__ Wv,
           const float* __restrict__ Wr) {
    if (blockIdx.z == 3) { router_body(x, Wr); return; }
    const float* W;
    float* C;
    if (blockIdx.z == 0)      { W = Wq; C = g_Q; }
    else if (blockIdx.z == 1) { W = Wk; C = g_K; }
    else                      { W = Wv; C = g_V; }
    gemm_tf32_body(x, W, C);
}

// ---------------------------------------------------------------------------
// RoPE + sigmoid + head-major transpose + Ksum (blocks 0..511)
// Per-head compaction (blocks 512..519); zero `out` (blocks 520..775)
// ---------------------------------------------------------------------------
__global__ void __launch_bounds__(256)
k_rope_sig(const float* __restrict__ fc, const float* __restrict__ fs,
           float* __restrict__ out) {
    const int t = threadIdx.x;

    if (blockIdx.x >= S_ + H_) {
        const int zb = blockIdx.x - (S_ + H_);
        *(float4*)&out[(zb * 256 + t) * 4] = make_float4(0.f, 0.f, 0.f, 0.f);
        return;
    }

    if (blockIdx.x >= S_) {
        const int h = blockIdx.x - S_;
        const int lane = t & 31, w = t >> 5;
        __shared__ int swc[16];
        const int s0 = t, s1 = t + 256;
        const int f0 = (g_gate[s0][h] != 0.f) ? 1 : 0;
        const int f1 = (g_gate[s1][h] != 0.f) ? 1 : 0;
        const unsigned b0 = __ballot_sync(0xFFFFFFFFu, f0);
        const unsigned b1 = __ballot_sync(0xFFFFFFFFu, f1);
        if (lane == 0) { swc[w] = __popc(b0); swc[8 + w] = __popc(b1); }
        __syncthreads();
        int pre0 = 0, tot0 = 0;
#pragma unroll
        for (int i = 0; i < 8; i++) {
            if (i < w) pre0 += swc[i];
            tot0 += swc[i];
        }
        int pre1 = tot0;
#pragma unroll
        for (int i = 0; i < 8; i++) if (i < w) pre1 += swc[8 + i];
        const unsigned lm = (1u << lane) - 1u;
        if (f0) g_qidx[h][pre0 + __popc(b0 & lm)] = s0;
        if (f1) g_qidx[h][pre1 + __popc(b1 & lm)] = s1;
        if (t == 0) {
            int tot = tot0;
#pragma unroll
            for (int i = 0; i < 8; i++) tot += swc[8 + i];
            g_qcnt[h] = tot;
        }
        return;
    }

    const int s = blockIdx.x;
    const int h = t >> 5, p = t & 31;

    const float c  = fc[s * HALF_ + p];
    const float sn = fs[s * HALF_ + p];
    const int base = s * DM_ + h * DH_ + 2 * p;

    float q0 = g_Q[base], q1 = g_Q[base + 1];
    float k0 = g_K[base], k1 = g_K[base + 1];
    float qr0 = q0 * c - q1 * sn, qr1 = q0 * sn + q1 * c;
    float kr0 = k0 * c - k1 * sn, kr1 = k0 * sn + k1 * c;
    float ks0 = sigf(kr0), ks1 = sigf(kr1);
    g_Qs[h][s][2 * p]     = sigf(qr0);
    g_Qs[h][s][2 * p + 1] = sigf(qr1);
    g_Ks[h][s][2 * p]     = ks0;
    g_Ks[h][s][2 * p + 1] = ks1;

    float v = ks0 + ks1;
#pragma unroll
    for (int o = 16; o > 0; o >>= 1)
        v += __shfl_xor_sync(0xFFFFFFFFu, v, o);
    if (p == 0) g_Ksum[h][s] = v;

#pragma unroll
    for (int j = t; j < DM_; j += 256) {
        int h2 = j >> 6, d = j & 63;
        g_Vh[h2][s][d] = g_V[s * DM_ + j];
    }
}

// ---------------------------------------------------------------------------
// Attention: 128 threads, 16 compacted queries, split-K x NSPL (=8).
// Writes slot-major partials: pacc[z][h][slot][d], prs[z][h][slot].
// ---------------------------------------------------------------------------
__global__ void __launch_bounds__(128)
k_attn() {
    const int h   = blockIdx.y;
    const int cnt = g_qcnt[h];
    const int q0  = blockIdx.x * QT;
    if (q0 >= cnt) return;
    const int nq  = min(QT, cnt - q0);
    const int z   = blockIdx.z;
    const int t   = threadIdx.x;

    __shared__ float Qs_s[QT][68];
    __shared__ float Ks_s[32][68];
    __shared__ float Vs_s[32][68];
    __shared__ float Tr  [QT][33];
    __shared__ float rs_s[QT];
    __shared__ float ksum_s[32];
    __shared__ int   sidx[QT];

    if (t < QT) {
        sidx[t] = g_qidx[h][q0 + ((t < nq) ? t : 0)];
        rs_s[t] = 0.f;
    }
    __syncthreads();

#pragma unroll
    for (int j = t; j < QT * 16; j += 128) {
        int r = j >> 4, c4 = (j & 15) << 2;
        *(float4*)&Qs_s[r][c4] = *(const float4*)&g_Qs[h][sidx[r]][c4];
    }

    const int qq = t >> 4, kk = t & 15;
    const int qa = 2 * qq, qb = qa + 1;
    const int ka = 2 * kk, kb = ka + 1;

    const int qf = t >> 3;
    const int dg = (t & 7) << 3;
    float acc[8] = {};
    const bool qf_active = (qf < nq);

    for (int kt = 0; kt < KPS / 32; kt++) {
        const int k0 = z * KPS + kt * 32;
        __syncthreads();
#pragma unroll
        for (int j = t; j < 32 * 16; j += 128) {
            int r = j >> 4, c4 = (j & 15) << 2;
            *(float4*)&Ks_s[r][c4] = *(const float4*)&g_Ks[h][k0 + r][c4];
            *(float4*)&Vs_s[r][c4] = *(const float4*)&g_Vh[h][k0 + r][c4];
        }
        if (t < 32) ksum_s[t] = g_Ksum[h][k0 + t];
        __syncthreads();

        {
            float s00 = 0.f, s01 = 0.f, s10 = 0.f, s11 = 0.f;
#pragma unroll
            for (int d = 0; d < 64; d += 4) {
                float4 A0 = *(const float4*)&Qs_s[qa][d];
                float4 A1 = *(const float4*)&Qs_s[qb][d];
                float4 B0 = *(const float4*)&Ks_s[ka][d];
                float4 B1 = *(const float4*)&Ks_s[kb][d];
                s00 += fmaxf(A0.x, B0.x) + fmaxf(A0.y, B0.y)
                     + fmaxf(A0.z, B0.z) + fmaxf(A0.w, B0.w);
                s01 += fmaxf(A0.x, B1.x) + fmaxf(A0.y, B1.y)
                     + fmaxf(A0.z, B1.z) + fmaxf(A0.w, B1.w);
                s10 += fmaxf(A1.x, B0.x) + fmaxf(A1.y, B0.y)
                     + fmaxf(A1.z, B0.z) + fmaxf(A1.w, B0.w);
                s11 += fmaxf(A1.x, B1.x) + fmaxf(A1.y, B1.y)
                     + fmaxf(A1.z, B1.z) + fmaxf(A1.w, B1.w);
            }
            const float c = 1.0f / 64.0f;
            const float ksa = ksum_s[ka], ksb = ksum_s[kb];
            Tr[qa][ka] = 1.0f - (s00 - ksa) * c;
            Tr[qa][kb] = 1.0f - (s01 - ksb) * c;
            Tr[qb][ka] = 1.0f - (s10 - ksa) * c;
            Tr[qb][kb] = 1.0f - (s11 - ksb) * c;
        }
        __syncthreads();

        if (t < QT) {
            float r = 0.f;
#pragma unroll
            for (int k = 0; k < 32; k++) r += Tr[t][k];
            rs_s[t] += r;
        }

#pragma unroll
        for (int k = 0; k < 32; k++) {
            float tv = Tr[qf][k];
            float4 v0 = *(const float4*)&Vs_s[k][dg];
            float4 v1 = *(const float4*)&Vs_s[k][dg + 4];
            acc[0] = fmaf(tv, v0.x, acc[0]);
            acc[1] = fmaf(tv, v0.y, acc[1]);
            acc[2] = fmaf(tv, v0.z, acc[2]);
            acc[3] = fmaf(tv, v0.w, acc[3]);
            acc[4] = fmaf(tv, v1.x, acc[4]);
            acc[5] = fmaf(tv, v1.y, acc[5]);
            acc[6] = fmaf(tv, v1.z, acc[6]);
            acc[7] = fmaf(tv, v1.w, acc[7]);
        }
    }
    __syncthreads();

    if (qf_active) {
        *(float4*)&g_pacc[z][h][q0 + qf][dg] =
            make_float4(acc[0], acc[1], acc[2], acc[3]);
        *(float4*)&g_pacc[z][h][q0 + qf][dg + 4] =
            make_float4(acc[4], acc[5], acc[6], acc[7]);
    }
    if (t < nq) g_prs[z][h][q0 + t] = rs_s[t];
}

// ---------------------------------------------------------------------------
// Combine splits + gate -> compact Gc[h][slot][d].  Fully coalesced:
// block = 16 slots x 16 float4-threads; pacc is slot-major contiguous.
// ---------------------------------------------------------------------------
__global__ void __launch_bounds__(256)
k_norm() {
    const int h   = blockIdx.y;
    const int cnt = g_qcnt[h];
    const int q0  = blockIdx.x * 16;
    if (q0 >= cnt) return;
    const int t  = threadIdx.x;
    const int sl = q0 + (t >> 4);
    if (sl >= cnt) return;
    const int d = (t & 15) << 2;
    const int s = g_qidx[h][sl];

    float rs = 0.f;
#pragma unroll
    for (int z = 0; z < NSPL; z++) rs += g_prs[z][h][sl];
    float4 sum = make_float4(0.f, 0.f, 0.f, 0.f);
#pragma unroll
    for (int z = 0; z < NSPL; z++) {
        float4 a = *(const float4*)&g_pacc[z][h][sl][d];
        sum.x += a.x; sum.y += a.y; sum.z += a.z; sum.w += a.w;
    }
    const float f = g_gate[s][h] / (rs + 1e-9f);
    *(float4*)&g_Gc[h][sl][d] =
        make_float4(sum.x * f, sum.y * f, sum.z * f, sum.w * f);
}

// ---------------------------------------------------------------------------
// Sparse output GEMM: out[qidx[sl]][n] += sum_k Gc[h][sl][k]*sig(Wo[n][h*64+k])
// K=64 (2 BK=32 chunks), scatter-atomicAdd epilogue; pad slots skipped.
// ---------------------------------------------------------------------------
__global__ void __launch_bounds__(256)
k_gemm_out_sp(const float* __restrict__ Wo, float* __restrict__ out) {
    const int h   = blockIdx.z;
    const int cnt = g_qcnt[h];
    const int m0  = blockIdx.y * 64;
    if (m0 >= cnt) return;
    const int n0  = blockIdx.x * 64;

    __shared__ float As[64][36];
    __shared__ float Bs[64][36];

    const int t    = threadIdx.x;
    const int lane = t & 31, w = t >> 5;
    const int wm = w & 1, wn = w >> 1;
    const int g  = lane >> 2, tg = lane & 3;
    const int rowL = t >> 2;
    const int cL   = (t & 3) << 3;

    float acc[2][2][4] = {};

    for (int ch = 0; ch < 2; ch++) {
        const int k0 = ch * 32;
        const int sl = m0 + rowL;                 // <= 511 always
        const float* Ar = &g_Gc[h][sl][k0 + cL];
        const float* Wr = Wo + (n0 + rowL) * DM_ + h * DH_ + k0 + cL;
        float4 a0 = *(const float4*)Ar;
        float4 a1 = *(const float4*)(Ar + 4);
        float4 b0 = *(const float4*)Wr;
        float4 b1 = *(const float4*)(Wr + 4);
        __syncthreads();
        *(float4*)&As[rowL][cL]     = a0;
        *(float4*)&As[rowL][cL + 4] = a1;
        *(float4*)&Bs[rowL][cL] =
            make_float4(sigf(b0.x), sigf(b0.y), sigf(b0.z), sigf(b0.w));
        *(float4*)&Bs[rowL][cL + 4] =
            make_float4(sigf(b1.x), sigf(b1.y), sigf(b1.z), sigf(b1.w));
        __syncthreads();

#pragma unroll
        for (int ks = 0; ks < 4; ks++) {
            const int kb = ks * 8;
            unsigned ah[2][4], al[2][4];
#pragma unroll
            for (int i = 0; i < 2; i++) {
                const int rm = wm * 32 + i * 16 + g;
                float v0 = As[rm    ][kb + tg];
                float v1 = As[rm + 8][kb + tg];
                float v2 = As[rm    ][kb + tg + 4];
                float v3 = As[rm + 8][kb + tg + 4];
                float hh, ll;
                hilo(v0, hh, ll); ah[i][0] = __float_as_uint(hh); al[i][0] = __float_as_uint(ll);
                hilo(v1, hh, ll); ah[i][1] = __float_as_uint(hh); al[i][1] = __float_as_uint(ll);
                hilo(v2, hh, ll); ah[i][2] = __float_as_uint(hh); al[i][2] = __float_as_uint(ll);
                hilo(v3, hh, ll); ah[i][3] = __float_as_uint(hh); al[i][3] = __float_as_uint(ll);
            }
            unsigned bh[2][2], bl[2][2];
#pragma unroll
            for (int j = 0; j < 2; j++) {
                const int rn = wn * 16 + j * 8 + g;
                float v0 = Bs[rn][kb + tg];
                float v1 = Bs[rn][kb + tg + 4];
                float hh, ll;
                hilo(v0, hh, ll); bh[j][0] = __float_as_uint(hh); bl[j][0] = __float_as_uint(ll);
                hilo(v1, hh, ll); bh[j][1] = __float_as_uint(hh); bl[j][1] = __float_as_uint(ll);
            }
#pragma unroll
            for (int i = 0; i < 2; i++)
#pragma unroll
                for (int j = 0; j < 2; j++) {
                    mma_tf32(acc[i][j], ah[i], bl[j]);
                    mma_tf32(acc[i][j], al[i], bh[j]);
                    mma_tf32(acc[i][j], ah[i], bh[j]);
                }
        }
    }

    // scatter epilogue: atomicAdd into out rows g_qidx[h][slot]
#pragma unroll
    for (int i = 0; i < 2; i++)
#pragma unroll
        for (int j = 0; j < 2; j++) {
            const int sl0 = m0 + wm * 32 + i * 16 + g;
            const int sl1 = sl0 + 8;
            const int gn  = n0 + wn * 16 + j * 8 + tg * 2;
            if (sl0 < cnt) {
                const int s = g_qidx[h][sl0];
                atomicAdd(&out[s * DM_ + gn],     acc[i][j][0]);
                atomicAdd(&out[s * DM_ + gn + 1], acc[i][j][1]);
            }
            if (sl1 < cnt) {
                const int s = g_qidx[h][sl1];
                atomicAdd(&out[s * DM_ + gn],     acc[i][j][2]);
                atomicAdd(&out[s * DM_ + gn + 1], acc[i][j][3]);
            }
        }
}

// ---------------------------------------------------------------------------
extern "C" void kernel_launch(void* const* d_in, const int* in_sizes, int n_in,
                              void* d_out, int out_size) {
    const float* x  = (const float*)d_in[0];
    const float* fc = (const float*)d_in[1];
    const float* fs = (const float*)d_in[2];
    const float* Wq = (const float*)d_in[3];
    const float* Wk = (const float*)d_in[4];
    const float* Wv = (const float*)d_in[5];
    const float* Wo = (const float*)d_in[6];
    const float* Wr = (const float*)d_in[7];
    float* out = (float*)d_out;

    k_gemm_qkv   <<<dim3(8, 8, 4), 256>>>(x, Wq, Wk, Wv, Wr);
    k_rope_sig   <<<S_ + H_ + 256, 256>>>(fc, fs, out);
    k_attn       <<<dim3(S_ / QT, H_, NSPL), 128>>>();
    k_norm       <<<dim3(32, H_), 256>>>();
    k_gemm_out_sp<<<dim3(8, 8, H_), 256>>>(Wo, out);
}

// round 17
// speedup vs baseline: 1.1059x; 1.0004x over previous
#include <cuda_runtime.h>

// ---------------------------------------------------------------------------
// MultiUniverseToposAttention  B=1 S=512 H=8 DH=64 DM=512 TOP_K=2
//   1) k_gemm_qkv (z=0..2): Q,K,V = x @ sig(W)^T via 3xTF32 mma.sync
//      (z=3): router gates (logits -> softmax -> top2), reads x only
//   2) k_rope_sig (grid 520+256): RoPE+sigmoid -> head-major Qs,Ks,Vh + Ksum;
//      per-head ballot-scan compaction; tail blocks zero `out`
//   3) k_attn (128 thr, 16-q tiles, split-K x8): truth = 1-(summax-Ksum)/64
//      partials SLOT-major; LAST split block per (h,tile) combines splits +
//      applies gate -> Gc[h][slot][64]  (threadfence-reduction; counter
//      self-resets -> graph-replay safe; fixed z order -> deterministic)
//   4) k_gemm_out_sp: per-head gather-GEMM (K=64) on Gc, scatter-atomicAdd
//      epilogue (2 commutative fp32 adds per element -> deterministic)
// ---------------------------------------------------------------------------

#define S_    512
#define DM_   512
#define H_    8
#define DH_   64
#define HALF_ 32
#define NSPL  8
#define KPS   (S_ / NSPL)
#define QT    16

__device__ float g_Q [S_ * DM_];
__device__ float g_K [S_ * DM_];
__device__ float g_V [S_ * DM_];
__device__ float g_Qs[H_][S_][DH_];
__device__ float g_Ks[H_][S_][DH_];
__device__ float g_Vh[H_][S_][DH_];
__device__ float g_Ksum[H_][S_];
__device__ float g_gate[S_][H_];
__device__ int   g_qidx[H_][S_];
__device__ int   g_qcnt[H_];
__device__ float g_Gc[H_][S_][DH_];           // compacted, gated attn output
__device__ float g_pacc[NSPL][H_][S_][DH_];   // slot-major split partials
__device__ float g_prs [NSPL][H_][S_];
__device__ int   g_tile_cnt[H_][S_ / QT];     // split-completion counters

__device__ __forceinline__ float sigf(float x) {
    return 1.0f / (1.0f + __expf(-x));
}
__device__ __forceinline__ unsigned f2tf(float x) {
    unsigned u;
    asm("cvt.rna.tf32.f32 %0, %1;" : "=r"(u) : "f"(x));
    return u;
}
__device__ __forceinline__ void hilo(float v, float& h, float& l) {
    unsigned hu = f2tf(v);
    h = __uint_as_float(hu);
    l = __uint_as_float(f2tf(v - h));
}
__device__ __forceinline__ void mma_tf32(float c[4], const unsigned a[4],
                                         const unsigned b[2]) {
    asm volatile(
        "mma.sync.aligned.m16n8k8.row.col.f32.tf32.tf32.f32 "
        "{%0,%1,%2,%3}, {%4,%5,%6,%7}, {%8,%9}, {%0,%1,%2,%3};"
        : "+f"(c[0]), "+f"(c[1]), "+f"(c[2]), "+f"(c[3])
        : "r"(a[0]), "r"(a[1]), "r"(a[2]), "r"(a[3]), "r"(b[0]), "r"(b[1]));
}

// ---------------------------------------------------------------------------
// Dense 3xTF32 GEMM (R11-validated): C = A @ sig(W)^T; 64x64 tile, BK=32.
// ---------------------------------------------------------------------------
__device__ __forceinline__ void gemm_tf32_body(const float* __restrict__ A,
                                               const float* __restrict__ W,
                                               float* __restrict__ C) {
    __shared__ float Ah[64][36];
    __shared__ float Al[64][36];
    __shared__ float Bh[64][36];
    __shared__ float Bl[64][36];

    const int t    = threadIdx.x;
    const int lane = t & 31, w = t >> 5;
    const int wm = w & 1, wn = w >> 1;
    const int g  = lane >> 2, tg = lane & 3;
    const int m0 = blockIdx.y * 64, n0 = blockIdx.x * 64;

    const int rowL = t >> 2;
    const int cL   = (t & 3) << 3;

    float4 pa0, pa1, pb0, pb1;
    {
        const float* Ar = A + (m0 + rowL) * DM_;
        const float* Wr = W + (n0 + rowL) * DM_;
        pa0 = *(const float4*)&Ar[cL];
        pa1 = *(const float4*)&Ar[cL + 4];
        pb0 = *(const float4*)&Wr[cL];
        pb1 = *(const float4*)&Wr[cL + 4];
    }

    float acc[2][2][4] = {};

    for (int ch = 0; ch < 16; ch++) {
        __syncthreads();
        {
            float4 h4, l4;
            hilo(pa0.x, h4.x, l4.x); hilo(pa0.y, h4.y, l4.y);
            hilo(pa0.z, h4.z, l4.z); hilo(pa0.w, h4.w, l4.w);
            *(float4*)&Ah[rowL][cL] = h4;
            *(float4*)&Al[rowL][cL] = l4;
            hilo(pa1.x, h4.x, l4.x); hilo(pa1.y, h4.y, l4.y);
            hilo(pa1.z, h4.z, l4.z); hilo(pa1.w, h4.w, l4.w);
            *(float4*)&Ah[rowL][cL + 4] = h4;
            *(float4*)&Al[rowL][cL + 4] = l4;
            hilo(sigf(pb0.x), h4.x, l4.x); hilo(sigf(pb0.y), h4.y, l4.y);
            hilo(sigf(pb0.z), h4.z, l4.z); hilo(sigf(pb0.w), h4.w, l4.w);
            *(float4*)&Bh[rowL][cL] = h4;
            *(float4*)&Bl[rowL][cL] = l4;
            hilo(sigf(pb1.x), h4.x, l4.x); hilo(sigf(pb1.y), h4.y, l4.y);
            hilo(sigf(pb1.z), h4.z, l4.z); hilo(sigf(pb1.w), h4.w, l4.w);
            *(float4*)&Bh[rowL][cL + 4] = h4;
            *(float4*)&Bl[rowL][cL + 4] = l4;
        }
        __syncthreads();

        if (ch < 15) {
            const int k0 = (ch + 1) * 32;
            const float* Ar = A + (m0 + rowL) * DM_ + k0;
            const float* Wr = W + (n0 + rowL) * DM_ + k0;
            pa0 = *(const float4*)&Ar[cL];
            pa1 = *(const float4*)&Ar[cL + 4];
            pb0 = *(const float4*)&Wr[cL];
            pb1 = *(const float4*)&Wr[cL + 4];
        }

#pragma unroll
        for (int ks = 0; ks < 4; ks++) {
            const int kb = ks * 8;
            unsigned ah[2][4], al[2][4];
#pragma unroll
            for (int i = 0; i < 2; i++) {
                const int rm = wm * 32 + i * 16 + g;
                ah[i][0] = __float_as_uint(Ah[rm    ][kb + tg]);
                ah[i][1] = __float_as_uint(Ah[rm + 8][kb + tg]);
                ah[i][2] = __float_as_uint(Ah[rm    ][kb + tg + 4]);
                ah[i][3] = __float_as_uint(Ah[rm + 8][kb + tg + 4]);
                al[i][0] = __float_as_uint(Al[rm    ][kb + tg]);
                al[i][1] = __float_as_uint(Al[rm + 8][kb + tg]);
                al[i][2] = __float_as_uint(Al[rm    ][kb + tg + 4]);
                al[i][3] = __float_as_uint(Al[rm + 8][kb + tg + 4]);
            }
            unsigned bh[2][2], bl[2][2];
#pragma unroll
            for (int j = 0; j < 2; j++) {
                const int rn = wn * 16 + j * 8 + g;
                bh[j][0] = __float_as_uint(Bh[rn][kb + tg]);
                bh[j][1] = __float_as_uint(Bh[rn][kb + tg + 4]);
                bl[j][0] = __float_as_uint(Bl[rn][kb + tg]);
                bl[j][1] = __float_as_uint(Bl[rn][kb + tg + 4]);
            }
#pragma unroll
            for (int i = 0; i < 2; i++)
#pragma unroll
                for (int j = 0; j < 2; j++) {
                    mma_tf32(acc[i][j], ah[i], bl[j]);
                    mma_tf32(acc[i][j], al[i], bh[j]);
                    mma_tf32(acc[i][j], ah[i], bh[j]);
                }
        }
    }

#pragma unroll
    for (int i = 0; i < 2; i++)
#pragma unroll
        for (int j = 0; j < 2; j++) {
            const int gm = m0 + wm * 32 + i * 16 + g;
            const int gn = n0 + wn * 16 + j * 8 + tg * 2;
            *(float2*)&C[gm * DM_ + gn]       = make_float2(acc[i][j][0], acc[i][j][1]);
            *(float2*)&C[(gm + 8) * DM_ + gn] = make_float2(acc[i][j][2], acc[i][j][3]);
        }
}

// ---------------------------------------------------------------------------
// Router body (z=3): 64 blocks x 8 warps = 512 tokens; warp per token.
// ---------------------------------------------------------------------------
__device__ __forceinline__ void router_body(const float* __restrict__ x,
                                            const float* __restrict__ Wr) {
    const int t = threadIdx.x;
    const int lane = t & 31, w = t >> 5;
    const int s = (blockIdx.y * 8 + blockIdx.x) * 8 + w;

    const float* xs = x + s * DM_;
    float acc[H_] = {};
#pragma unroll 4
    for (int ds = 0; ds < 16; ds++) {
        const int d = lane + 32 * ds;
        const float xv = xs[d];
#pragma unroll
        for (int h = 0; h < H_; h++)
            acc[h] = fmaf(xv, sigf(Wr[h * DM_ + d]), acc[h]);
    }
#pragma unroll
    for (int h = 0; h < H_; h++)
#pragma unroll
        for (int o = 16; o > 0; o >>= 1)
            acc[h] += __shfl_xor_sync(0xFFFFFFFFu, acc[h], o);

    if (lane == 0) {
        float m = acc[0];
#pragma unroll
        for (int i = 1; i < H_; i++) m = fmaxf(m, acc[i]);
        float e[H_];
        float Z = 0.f;
#pragma unroll
        for (int i = 0; i < H_; i++) { e[i] = expf(acc[i] - m); Z += e[i]; }
        int i0 = 0;
#pragma unroll
        for (int i = 1; i < H_; i++) if (e[i] > e[i0]) i0 = i;
        int i1 = (i0 == 0) ? 1 : 0;
#pragma unroll
        for (int i = 0; i < H_; i++) if (i != i0 && e[i] > e[i1]) i1 = i;
        float p0 = e[i0] / Z, p1 = e[i1] / Z;
        float inv = 1.0f / (p0 + p1 + 1e-9f);
#pragma unroll
        for (int i = 0; i < H_; i++) g_gate[s][i] = 0.f;
        g_gate[s][i0] = p0 * inv;
        g_gate[s][i1] = p1 * inv;
    }
}

__global__ void __launch_bounds__(256)
k_gemm_qkv(const float* __restrict__ x,
           const float* __restrict__ Wq,
           const float* __restrict__ Wk,
           const float* __restrict__ Wv,
           const float* __restrict__ Wr) {
    if (blockIdx.z == 3) { router_body(x, Wr); return; }
    const float* W;
    float* C;
    if (blockIdx.z == 0)      { W = Wq; C = g_Q; }
    else if (blockIdx.z == 1) { W = Wk; C = g_K; }
    else                      { W = Wv; C = g_V; }
    gemm_tf32_body(x, W, C);
}

// ---------------------------------------------------------------------------
// RoPE + sigmoid + head-major transpose + Ksum (blocks 0..511)
// Per-head compaction (blocks 512..519); zero `out` (blocks 520..775)
// ---------------------------------------------------------------------------
__global__ void __launch_bounds__(256)
k_rope_sig(const float* __restrict__ fc, const float* __restrict__ fs,
           float* __restrict__ out) {
    const int t = threadIdx.x;

    if (blockIdx.x >= S_ + H_) {
        const int zb = blockIdx.x - (S_ + H_);
        *(float4*)&out[(zb * 256 + t) * 4] = make_float4(0.f, 0.f, 0.f, 0.f);
        return;
    }

    if (blockIdx.x >= S_) {
        const int h = blockIdx.x - S_;
        const int lane = t & 31, w = t >> 5;
        __shared__ int swc[16];
        const int s0 = t, s1 = t + 256;
        const int f0 = (g_gate[s0][h] != 0.f) ? 1 : 0;
        const int f1 = (g_gate[s1][h] != 0.f) ? 1 : 0;
        const unsigned b0 = __ballot_sync(0xFFFFFFFFu, f0);
        const unsigned b1 = __ballot_sync(0xFFFFFFFFu, f1);
        if (lane == 0) { swc[w] = __popc(b0); swc[8 + w] = __popc(b1); }
        __syncthreads();
        int pre0 = 0, tot0 = 0;
#pragma unroll
        for (int i = 0; i < 8; i++) {
            if (i < w) pre0 += swc[i];
            tot0 += swc[i];
        }
        int pre1 = tot0;
#pragma unroll
        for (int i = 0; i < 8; i++) if (i < w) pre1 += swc[8 + i];
        const unsigned lm = (1u << lane) - 1u;
        if (f0) g_qidx[h][pre0 + __popc(b0 & lm)] = s0;
        if (f1) g_qidx[h][pre1 + __popc(b1 & lm)] = s1;
        if (t == 0) {
            int tot = tot0;
#pragma unroll
            for (int i = 0; i < 8; i++) tot += swc[8 + i];
            g_qcnt[h] = tot;
        }
        return;
    }

    const int s = blockIdx.x;
    const int h = t >> 5, p = t & 31;

    const float c  = fc[s * HALF_ + p];
    const float sn = fs[s * HALF_ + p];
    const int base = s * DM_ + h * DH_ + 2 * p;

    float q0 = g_Q[base], q1 = g_Q[base + 1];
    float k0 = g_K[base], k1 = g_K[base + 1];
    float qr0 = q0 * c - q1 * sn, qr1 = q0 * sn + q1 * c;
    float kr0 = k0 * c - k1 * sn, kr1 = k0 * sn + k1 * c;
    float ks0 = sigf(kr0), ks1 = sigf(kr1);
    g_Qs[h][s][2 * p]     = sigf(qr0);
    g_Qs[h][s][2 * p + 1] = sigf(qr1);
    g_Ks[h][s][2 * p]     = ks0;
    g_Ks[h][s][2 * p + 1] = ks1;

    float v = ks0 + ks1;
#pragma unroll
    for (int o = 16; o > 0; o >>= 1)
        v += __shfl_xor_sync(0xFFFFFFFFu, v, o);
    if (p == 0) g_Ksum[h][s] = v;

#pragma unroll
    for (int j = t; j < DM_; j += 256) {
        int h2 = j >> 6, d = j & 63;
        g_Vh[h2][s][d] = g_V[s * DM_ + j];
    }
}

// ---------------------------------------------------------------------------
// Attention: 128 threads, 16 compacted queries, split-K x NSPL (=8).
// Writes slot-major partials; the LAST split block per (h,tile) combines all
// splits + applies gate -> Gc (threadfence reduction, self-resetting counter).
// ---------------------------------------------------------------------------
__global__ void __launch_bounds__(128)
k_attn() {
    const int h   = blockIdx.y;
    const int cnt = g_qcnt[h];
    const int q0  = blockIdx.x * QT;
    if (q0 >= cnt) return;
    const int nq  = min(QT, cnt - q0);
    const int z   = blockIdx.z;
    const int t   = threadIdx.x;

    __shared__ float Qs_s[QT][68];
    __shared__ float Ks_s[32][68];
    __shared__ float Vs_s[32][68];
    __shared__ float Tr  [QT][33];
    __shared__ float rs_s[QT];
    __shared__ float ksum_s[32];
    __shared__ int   sidx[QT];
    __shared__ int   is_last;
    __shared__ float fscale[QT];

    if (t < QT) {
        sidx[t] = g_qidx[h][q0 + ((t < nq) ? t : 0)];
        rs_s[t] = 0.f;
    }
    __syncthreads();

#pragma unroll
    for (int j = t; j < QT * 16; j += 128) {
        int r = j >> 4, c4 = (j & 15) << 2;
        *(float4*)&Qs_s[r][c4] = *(const float4*)&g_Qs[h][sidx[r]][c4];
    }

    const int qq = t >> 4, kk = t & 15;
    const int qa = 2 * qq, qb = qa + 1;
    const int ka = 2 * kk, kb = ka + 1;

    const int qf = t >> 3;
    const int dg = (t & 7) << 3;
    float acc[8] = {};
    const bool qf_active = (qf < nq);

    for (int kt = 0; kt < KPS / 32; kt++) {
        const int k0 = z * KPS + kt * 32;
        __syncthreads();
#pragma unroll
        for (int j = t; j < 32 * 16; j += 128) {
            int r = j >> 4, c4 = (j & 15) << 2;
            *(float4*)&Ks_s[r][c4] = *(const float4*)&g_Ks[h][k0 + r][c4];
            *(float4*)&Vs_s[r][c4] = *(const float4*)&g_Vh[h][k0 + r][c4];
        }
        if (t < 32) ksum_s[t] = g_Ksum[h][k0 + t];
        __syncthreads();

        {
            float s00 = 0.f, s01 = 0.f, s10 = 0.f, s11 = 0.f;
#pragma unroll
            for (int d = 0; d < 64; d += 4) {
                float4 A0 = *(const float4*)&Qs_s[qa][d];
                float4 A1 = *(const float4*)&Qs_s[qb][d];
                float4 B0 = *(const float4*)&Ks_s[ka][d];
                float4 B1 = *(const float4*)&Ks_s[kb][d];
                s00 += fmaxf(A0.x, B0.x) + fmaxf(A0.y, B0.y)
                     + fmaxf(A0.z, B0.z) + fmaxf(A0.w, B0.w);
                s01 += fmaxf(A0.x, B1.x) + fmaxf(A0.y, B1.y)
                     + fmaxf(A0.z, B1.z) + fmaxf(A0.w, B1.w);
                s10 += fmaxf(A1.x, B0.x) + fmaxf(A1.y, B0.y)
                     + fmaxf(A1.z, B0.z) + fmaxf(A1.w, B0.w);
                s11 += fmaxf(A1.x, B1.x) + fmaxf(A1.y, B1.y)
                     + fmaxf(A1.z, B1.z) + fmaxf(A1.w, B1.w);
            }
            const float c = 1.0f / 64.0f;
            const float ksa = ksum_s[ka], ksb = ksum_s[kb];
            Tr[qa][ka] = 1.0f - (s00 - ksa) * c;
            Tr[qa][kb] = 1.0f - (s01 - ksb) * c;
            Tr[qb][ka] = 1.0f - (s10 - ksa) * c;
            Tr[qb][kb] = 1.0f - (s11 - ksb) * c;
        }
        __syncthreads();

        if (t < QT) {
            float r = 0.f;
#pragma unroll
            for (int k = 0; k < 32; k++) r += Tr[t][k];
            rs_s[t] += r;
        }

#pragma unroll
        for (int k = 0; k < 32; k++) {
            float tv = Tr[qf][k];
            float4 v0 = *(const float4*)&Vs_s[k][dg];
            float4 v1 = *(const float4*)&Vs_s[k][dg + 4];
            acc[0] = fmaf(tv, v0.x, acc[0]);
            acc[1] = fmaf(tv, v0.y, acc[1]);
            acc[2] = fmaf(tv, v0.z, acc[2]);
            acc[3] = fmaf(tv, v0.w, acc[3]);
            acc[4] = fmaf(tv, v1.x, acc[4]);
            acc[5] = fmaf(tv, v1.y, acc[5]);
            acc[6] = fmaf(tv, v1.z, acc[6]);
            acc[7] = fmaf(tv, v1.w, acc[7]);
        }
    }
    __syncthreads();

    if (qf_active) {
        *(float4*)&g_pacc[z][h][q0 + qf][dg] =
            make_float4(acc[0], acc[1], acc[2], acc[3]);
        *(float4*)&g_pacc[z][h][q0 + qf][dg + 4] =
            make_float4(acc[4], acc[5], acc[6], acc[7]);
    }
    if (t < nq) g_prs[z][h][q0 + t] = rs_s[t];

    // ---- last-block split combine (replaces k_norm) ----
    __threadfence();
    if (t == 0) {
        int old = atomicAdd(&g_tile_cnt[h][blockIdx.x], 1);
        is_last = (old == NSPL - 1) ? 1 : 0;
    }
    __syncthreads();
    if (!is_last) return;

    // per-slot scale f = gate/(rs+eps)
    if (t < QT) {
        float f = 0.f;
        if (t < nq) {
            float rs = 0.f;
#pragma unroll
            for (int zz = 0; zz < NSPL; zz++) rs += g_prs[zz][h][q0 + t];
            f = g_gate[sidx[t]][h] / (rs + 1e-9f);
        }
        fscale[t] = f;
    }
    __syncthreads();

    // combine 16 slots x 16 float4 cols (256 items, 128 threads x 2)
#pragma unroll
    for (int it = t; it < QT * 16; it += 128) {
        const int ls = it >> 4;
        if (ls < nq) {
            const int sl = q0 + ls;
            const int d  = (it & 15) << 2;
            float4 sum = make_float4(0.f, 0.f, 0.f, 0.f);
#pragma unroll
            for (int zz = 0; zz < NSPL; zz++) {
                float4 a = *(const float4*)&g_pacc[zz][h][sl][d];
                sum.x += a.x; sum.y += a.y; sum.z += a.z; sum.w += a.w;
            }
            const float f = fscale[ls];
            *(float4*)&g_Gc[h][sl][d] =
                make_float4(sum.x * f, sum.y * f, sum.z * f, sum.w * f);
        }
    }
    if (t == 0) g_tile_cnt[h][blockIdx.x] = 0;   // reset for next replay
}

// ---------------------------------------------------------------------------
// Sparse output GEMM: out[qidx[sl]][n] += sum_k Gc[h][sl][k]*sig(Wo[n][h*64+k])
// K=64 (2 BK=32 chunks), scatter-atomicAdd epilogue; pad slots skipped.
// ---------------------------------------------------------------------------
__global__ void __launch_bounds__(256)
k_gemm_out_sp(const float* __restrict__ Wo, float* __restrict__ out) {
    const int h   = blockIdx.z;
    const int cnt = g_qcnt[h];
    const int m0  = blockIdx.y * 64;
    if (m0 >= cnt) return;
    const int n0  = blockIdx.x * 64;

    __shared__ float As[64][36];
    __shared__ float Bs[64][36];

    const int t    = threadIdx.x;
    const int lane = t & 31, w = t >> 5;
    const int wm = w & 1, wn = w >> 1;
    const int g  = lane >> 2, tg = lane & 3;
    const int rowL = t >> 2;
    const int cL   = (t & 3) << 3;

    float acc[2][2][4] = {};

    for (int ch = 0; ch < 2; ch++) {
        const int k0 = ch * 32;
        const int sl = m0 + rowL;                 // <= 511 always
        const float* Ar = &g_Gc[h][sl][k0 + cL];
        const float* Wr = Wo + (n0 + rowL) * DM_ + h * DH_ + k0 + cL;
        float4 a0 = *(const float4*)Ar;
        float4 a1 = *(const float4*)(Ar + 4);
        float4 b0 = *(const float4*)Wr;
        float4 b1 = *(const float4*)(Wr + 4);
        __syncthreads();
        *(float4*)&As[rowL][cL]     = a0;
        *(float4*)&As[rowL][cL + 4] = a1;
        *(float4*)&Bs[rowL][cL] =
            make_float4(sigf(b0.x), sigf(b0.y), sigf(b0.z), sigf(b0.w));
        *(float4*)&Bs[rowL][cL + 4] =
            make_float4(sigf(b1.x), sigf(b1.y), sigf(b1.z), sigf(b1.w));
        __syncthreads();

#pragma unroll
        for (int ks = 0; ks < 4; ks++) {
            const int kb = ks * 8;
            unsigned ah[2][4], al[2][4];
#pragma unroll
            for (int i = 0; i < 2; i++) {
                const int rm = wm * 32 + i * 16 + g;
                float v0 = As[rm    ][kb + tg];
                float v1 = As[rm + 8][kb + tg];
                float v2 = As[rm    ][kb + tg + 4];
                float v3 = As[rm + 8][kb + tg + 4];
                float hh, ll;
                hilo(v0, hh, ll); ah[i][0] = __float_as_uint(hh); al[i][0] = __float_as_uint(ll);
                hilo(v1, hh, ll); ah[i][1] = __float_as_uint(hh); al[i][1] = __float_as_uint(ll);
                hilo(v2, hh, ll); ah[i][2] = __float_as_uint(hh); al[i][2] = __float_as_uint(ll);
                hilo(v3, hh, ll); ah[i][3] = __float_as_uint(hh); al[i][3] = __float_as_uint(ll);
            }
            unsigned bh[2][2], bl[2][2];
#pragma unroll
            for (int j = 0; j < 2; j++) {
                const int rn = wn * 16 + j * 8 + g;
                float v0 = Bs[rn][kb + tg];
                float v1 = Bs[rn][kb + tg + 4];
                float hh, ll;
                hilo(v0, hh, ll); bh[j][0] = __float_as_uint(hh); bl[j][0] = __float_as_uint(ll);
                hilo(v1, hh, ll); bh[j][1] = __float_as_uint(hh); bl[j][1] = __float_as_uint(ll);
            }
#pragma unroll
            for (int i = 0; i < 2; i++)
#pragma unroll
                for (int j = 0; j < 2; j++) {
                    mma_tf32(acc[i][j], ah[i], bl[j]);
                    mma_tf32(acc[i][j], al[i], bh[j]);
                    mma_tf32(acc[i][j], ah[i], bh[j]);
                }
        }
    }

    // scatter epilogue: atomicAdd into out rows g_qidx[h][slot]
#pragma unroll
    for (int i = 0; i < 2; i++)
#pragma unroll
        for (int j = 0; j < 2; j++) {
            const int sl0 = m0 + wm * 32 + i * 16 + g;
            const int sl1 = sl0 + 8;
            const int gn  = n0 + wn * 16 + j * 8 + tg * 2;
            if (sl0 < cnt) {
                const int s = g_qidx[h][sl0];
                atomicAdd(&out[s * DM_ + gn],     acc[i][j][0]);
                atomicAdd(&out[s * DM_ + gn + 1], acc[i][j][1]);
            }
            if (sl1 < cnt) {
                const int s = g_qidx[h][sl1];
                atomicAdd(&out[s * DM_ + gn],     acc[i][j][2]);
                atomicAdd(&out[s * DM_ + gn + 1], acc[i][j][3]);
            }
        }
}

// ---------------------------------------------------------------------------
extern "C" void kernel_launch(void* const* d_in, const int* in_sizes, int n_in,
                              void* d_out, int out_size) {
    const float* x  = (const float*)d_in[0];
    const float* fc = (const float*)d_in[1];
    const float* fs = (const float*)d_in[2];
    const float* Wq = (const float*)d_in[3];
    const float* Wk = (const float*)d_in[4];
    const float* Wv = (const float*)d_in[5];
    const float* Wo = (const float*)d_in[6];
    const float* Wr = (const float*)d_in[7];
    float* out = (float*)d_out;

    k_gemm_qkv   <<<dim3(8, 8, 4), 256>>>(x, Wq, Wk, Wv, Wr);
    k_rope_sig   <<<S_ + H_ + 256, 256>>>(fc, fs, out);
    k_attn       <<<dim3(S_ / QT, H_, NSPL), 128>>>();
    k_gemm_out_sp<<<dim3(8, 8, H_), 256>>>(Wo, out);
}